// round 11
// baseline (speedup 1.0000x reference)
#include <cuda_runtime.h>
#include <math.h>

#define D   4096
#define H   64
#define S   64
#define EPSF 1e-5f

// Scratch (allocation-free rule: __device__ globals)
__device__ float g_mix[4 * D];    // [r, k, v, g] mixed input vectors
__device__ float g_rkvg[4 * D];   // [r, k, v, g] matvec results
__device__ float g_y[D];          // gated, normalized wkv -> input to Wo

// ---------------------------------------------------------------------------
// mbarrier helpers
// ---------------------------------------------------------------------------
__device__ __forceinline__ unsigned smem_u32(const void* p)
{
    unsigned a;
    asm("{ .reg .u64 t; cvta.to.shared.u64 t, %1; cvt.u32.u64 %0, t; }"
        : "=r"(a) : "l"(p));
    return a;
}

#define MBAR_INIT(addr, cnt) \
    asm volatile("mbarrier.init.shared.b64 [%0], %1;" :: "r"(addr), "r"(cnt) : "memory")

#define MBAR_EXPECT_TX(addr, bytes) \
    asm volatile("mbarrier.arrive.expect_tx.shared.b64 _, [%0], %1;" \
                 :: "r"(addr), "r"(bytes) : "memory")

#define TMA_BULK_G2S(dst, src, bytes, mbar) \
    asm volatile("cp.async.bulk.shared::cluster.global.mbarrier::complete_tx::bytes " \
                 "[%0], [%1], %2, [%3];" \
                 :: "r"(dst), "l"(src), "r"(bytes), "r"(mbar) : "memory")

#define MBAR_WAIT_P0(addr) do {                                               \
    asm volatile("{\n\t.reg .pred p;\n\t"                                     \
                 "W_%=:\n\t"                                                  \
                 "mbarrier.try_wait.parity.acquire.cta.shared::cta.b64 p, [%0], 0, 0x989680;\n\t" \
                 "@!p bra W_%=;\n\t}"                                         \
                 :: "r"(addr) : "memory");                                    \
} while (0)

// ---------------------------------------------------------------------------
// Kernel 1: LayerNorm(x) + 4 token-mixes. Single block, 256 threads.
// ---------------------------------------------------------------------------
__global__ __launch_bounds__(256) void ln_mix_kernel(
    const float* __restrict__ x, const float* __restrict__ state1,
    const float* __restrict__ tmr, const float* __restrict__ tmk,
    const float* __restrict__ tmv, const float* __restrict__ tmg,
    const float* __restrict__ ln1_w, const float* __restrict__ ln1_b,
    float* __restrict__ state1_out)
{
    int tid = threadIdx.x;
    float4 xv[4];
    float s = 0.f, sq = 0.f;
#pragma unroll
    for (int k = 0; k < 4; k++) {
        xv[k] = ((const float4*)x)[tid + k * 256];
        s  += xv[k].x + xv[k].y + xv[k].z + xv[k].w;
        sq += xv[k].x * xv[k].x + xv[k].y * xv[k].y
            + xv[k].z * xv[k].z + xv[k].w * xv[k].w;
    }
    __shared__ float sa[8], sb[8];
#pragma unroll
    for (int o = 16; o; o >>= 1) {
        s  += __shfl_xor_sync(0xffffffffu, s, o);
        sq += __shfl_xor_sync(0xffffffffu, sq, o);
    }
    int w = tid >> 5, l = tid & 31;
    if (l == 0) { sa[w] = s; sb[w] = sq; }
    __syncthreads();
    __shared__ float s_mean, s_rstd;
    if (tid == 0) {
        float ts = 0.f, tq = 0.f;
#pragma unroll
        for (int i = 0; i < 8; i++) { ts += sa[i]; tq += sb[i]; }
        float m   = ts * (1.0f / D);
        float var = tq * (1.0f / D) - m * m;
        s_mean = m;
        s_rstd = rsqrtf(var + EPSF);
    }
    __syncthreads();
    float m = s_mean, rstd = s_rstd;

#pragma unroll
    for (int k = 0; k < 4; k++) {
        int idx = tid + k * 256;
        float4 w4 = ((const float4*)ln1_w)[idx];
        float4 b4 = ((const float4*)ln1_b)[idx];
        float4 st = ((const float4*)state1)[idx];
        float4 xx;
        xx.x = (xv[k].x - m) * rstd * w4.x + b4.x;
        xx.y = (xv[k].y - m) * rstd * w4.y + b4.y;
        xx.z = (xv[k].z - m) * rstd * w4.z + b4.z;
        xx.w = (xv[k].w - m) * rstd * w4.w + b4.w;
        ((float4*)state1_out)[idx] = xx;

        const float* tms[4] = {tmr, tmk, tmv, tmg};
#pragma unroll
        for (int mi = 0; mi < 4; mi++) {
            float4 t = ((const float4*)tms[mi])[idx];
            float4 o;
            o.x = st.x * (1.f - t.x) + xx.x * t.x;
            o.y = st.y * (1.f - t.y) + xx.y * t.y;
            o.z = st.z * (1.f - t.z) + xx.z * t.z;
            o.w = st.w * (1.f - t.w) + xx.w * t.w;
            ((float4*)(g_mix + mi * D))[idx] = o;
        }
    }
}

// ---------------------------------------------------------------------------
// TMA-streamed row dot: block loads one 16KB weight row via cp.async.bulk,
// prefetches its x-slice into registers during TMA flight, dots from smem.
// ---------------------------------------------------------------------------
struct RowResult { float val; };

__device__ __forceinline__ float tma_row_dot(
    const float* __restrict__ Wrow, const float* __restrict__ xvec)
{
    __shared__ __align__(128) float wrow[D];          // 16 KB
    __shared__ __align__(8)  unsigned long long mbar;
    __shared__ float part[8];

    int tid = threadIdx.x;
    unsigned mb = smem_u32(&mbar);
    if (tid == 0) {
        MBAR_INIT(mb, 1);
        asm volatile("fence.proxy.async.shared::cta;" ::: "memory");
    }
    __syncthreads();
    if (tid == 0) {
        MBAR_EXPECT_TX(mb, (unsigned)(D * 4));
        TMA_BULK_G2S(smem_u32(wrow), Wrow, (unsigned)(D * 4), mb);
    }

    int warp = tid >> 5, lane = tid & 31;
    int off  = warp * 512 + lane * 4;
    // x-slice prefetch overlaps the TMA flight
    float4 x0 = *(const float4*)(xvec + off + 0 * 128);
    float4 x1 = *(const float4*)(xvec + off + 1 * 128);
    float4 x2 = *(const float4*)(xvec + off + 2 * 128);
    float4 x3 = *(const float4*)(xvec + off + 3 * 128);

    MBAR_WAIT_P0(mb);

    float4 w0 = *(const float4*)(wrow + off + 0 * 128);
    float4 w1 = *(const float4*)(wrow + off + 1 * 128);
    float4 w2 = *(const float4*)(wrow + off + 2 * 128);
    float4 w3 = *(const float4*)(wrow + off + 3 * 128);

    float a0 = w0.x * x0.x + w0.y * x0.y + w0.z * x0.z + w0.w * x0.w;
    float a1 = w1.x * x1.x + w1.y * x1.y + w1.z * x1.z + w1.w * x1.w;
    float a2 = w2.x * x2.x + w2.y * x2.y + w2.z * x2.z + w2.w * x2.w;
    float a3 = w3.x * x3.x + w3.y * x3.y + w3.z * x3.z + w3.w * x3.w;
    float acc = (a0 + a1) + (a2 + a3);
#pragma unroll
    for (int o = 16; o; o >>= 1) acc += __shfl_xor_sync(0xffffffffu, acc, o);

    if (lane == 0) part[warp] = acc;
    __syncthreads();
    return ((part[0] + part[1]) + (part[2] + part[3]))
         + ((part[4] + part[5]) + (part[6] + part[7]));
}

// ---------------------------------------------------------------------------
// Kernel 2: fused 4x matvec (Wr,Wk,Wv,Wg). grid (4096, 4), block 256.
// ---------------------------------------------------------------------------
__global__ __launch_bounds__(256) void matvec4_kernel(
    const float* __restrict__ Wr, const float* __restrict__ Wk,
    const float* __restrict__ Wv, const float* __restrict__ Wg)
{
    int m = blockIdx.y;
    const float* W = (m == 0) ? Wr : (m == 1) ? Wk : (m == 2) ? Wv : Wg;
    float r = tma_row_dot(W + (size_t)blockIdx.x * D, g_mix + m * D);
    if (threadIdx.x == 0) g_rkvg[m * D + blockIdx.x] = r;
}

// ---------------------------------------------------------------------------
// Kernel 3: per-head WKV + state2 update + InstanceNorm + SiLU gate.
// grid = 64 heads, block = 256. float4 over j.
// ---------------------------------------------------------------------------
__global__ __launch_bounds__(256) void wkv_kernel(
    const float* __restrict__ state2, const float* __restrict__ time_decay,
    const float* __restrict__ time_first, const float* __restrict__ lnx_w,
    const float* __restrict__ lnx_b, float* __restrict__ state2_out)
{
    int h = blockIdx.x, t = threadIdx.x;
    int jg = t & 15, ig = t >> 4;

    const float4* S2  = (const float4*)(state2 + (size_t)h * S * S);
    float4*       S2o = (float4*)(state2_out + (size_t)h * S * S);

    float4 s2v[4];
#pragma unroll
    for (int di = 0; di < 4; di++)
        s2v[di] = S2[(ig * 4 + di) * 16 + jg];

    __shared__ float sk[S], sr[S], stf[S], sdec[S];
    __shared__ float pw[16][S];
    __shared__ float sw[S];
    if (t < S) {
        sr[t]   = g_rkvg[0 * D + h * S + t];
        sk[t]   = g_rkvg[1 * D + h * S + t];
        stf[t]  = time_first[h * S + t];
        sdec[t] = time_decay[h * S + t];
    }
    float4 vj = ((const float4*)(g_rkvg + 2 * D + h * S))[jg];
    __syncthreads();

    float4 acc = make_float4(0.f, 0.f, 0.f, 0.f);
#pragma unroll
    for (int di = 0; di < 4; di++) {
        int i = ig * 4 + di;
        float ki = sk[i], ri = sr[i], tfi = stf[i], dci = sdec[i];
        float4 s2 = s2v[di];
        float4 kv = make_float4(ki * vj.x, ki * vj.y, ki * vj.z, ki * vj.w);
        float4 so;
        so.x = kv.x + s2.x * dci; so.y = kv.y + s2.y * dci;
        so.z = kv.z + s2.z * dci; so.w = kv.w + s2.w * dci;
        S2o[i * 16 + jg] = so;
        acc.x += ri * (kv.x * tfi + s2.x);
        acc.y += ri * (kv.y * tfi + s2.y);
        acc.z += ri * (kv.z * tfi + s2.z);
        acc.w += ri * (kv.w * tfi + s2.w);
    }
    ((float4*)&pw[ig][0])[jg] = acc;
    __syncthreads();

    if (t < S) {
        float wsum = 0.f;
#pragma unroll
        for (int g2 = 0; g2 < 16; g2++) wsum += pw[g2][t];
        sw[t] = wsum;
    }
    __syncthreads();
    if (t < S) {
        float s = 0.f, sq = 0.f;
#pragma unroll
        for (int i = 0; i < S; i++) { float u = sw[i]; s += u; sq += u * u; }
        float mu  = s * (1.0f / S);
        float var = sq * (1.0f / S) - mu * mu;
        float xn  = (sw[t] - mu) * rsqrtf(var + EPSF);

        float g    = g_rkvg[3 * D + h * S + t];
        float gate = g / (1.f + expf(-g));   // SiLU
        g_y[h * S + t] = (xn * lnx_w[h * S + t] + lnx_b[h * S + t]) * gate;
    }
}

// ---------------------------------------------------------------------------
// Kernel 4: out = x + Wo @ y. grid = 4096, block 256. TMA-streamed rows.
// ---------------------------------------------------------------------------
__global__ __launch_bounds__(256) void matvec_out_kernel(
    const float* __restrict__ Wo, const float* __restrict__ x,
    float* __restrict__ out)
{
    int row = blockIdx.x;
    float r = tma_row_dot(Wo + (size_t)row * D, g_y);
    if (threadIdx.x == 0) out[row] = x[row] + r;
}

// ---------------------------------------------------------------------------
extern "C" void kernel_launch(void* const* d_in, const int* in_sizes, int n_in,
                              void* d_out, int out_size)
{
    const float* x      = (const float*)d_in[0];
    const float* state1 = (const float*)d_in[1];
    const float* state2 = (const float*)d_in[2];
    const float* tmk    = (const float*)d_in[3];
    const float* tmv    = (const float*)d_in[4];
    const float* tmr    = (const float*)d_in[5];
    const float* tmg    = (const float*)d_in[6];
    const float* tdec   = (const float*)d_in[7];
    const float* tfir   = (const float*)d_in[8];
    const float* Wr     = (const float*)d_in[9];
    const float* Wk     = (const float*)d_in[10];
    const float* Wv     = (const float*)d_in[11];
    const float* Wg     = (const float*)d_in[12];
    const float* Wo     = (const float*)d_in[13];
    const float* ln1w   = (const float*)d_in[14];
    const float* ln1b   = (const float*)d_in[15];
    const float* lnxw   = (const float*)d_in[16];
    const float* lnxb   = (const float*)d_in[17];

    float* out        = (float*)d_out;         // [0, D)
    float* state1_out = out + D;               // [D, 2D)
    float* state2_out = out + 2 * D;           // [2D, 2D + H*S*S)

    ln_mix_kernel<<<1, 256>>>(x, state1, tmr, tmk, tmv, tmg, ln1w, ln1b,
                              state1_out);
    matvec4_kernel<<<dim3(4096, 4), 256>>>(Wr, Wk, Wv, Wg);
    wkv_kernel<<<64, 256>>>(state2, tdec, tfir, lnxw, lnxb, state2_out);
    matvec_out_kernel<<<4096, 256>>>(Wo, x, out);
}

// round 15
// speedup vs baseline: 1.0408x; 1.0408x over previous
#include <cuda_runtime.h>
#include <math.h>

#define D    4096
#define H    64
#define S    64
#define EPSF 1e-5f
#define NBLK 512
#define NTHR 256

// Scratch (allocation-free rule: __device__ globals)
__device__ __align__(16) float g_mix[4 * D];   // [r, k, v, g] mixed vectors
__device__ __align__(16) float g_rkvg[4 * D];  // [r, k, v, g] matvec results
__device__ __align__(16) float g_y[D];         // gated normalized wkv
__device__ unsigned g_count = 0;  // grid barrier arrival counter
__device__ unsigned g_gen   = 0;  // grid barrier generation

// ---------------------------------------------------------------------------
// PTX helpers
// ---------------------------------------------------------------------------
__device__ __forceinline__ unsigned smem_u32(const void* p)
{
    unsigned a;
    asm("{ .reg .u64 t; cvta.to.shared.u64 t, %1; cvt.u32.u64 %0, t; }"
        : "=r"(a) : "l"(p));
    return a;
}

#define MBAR_INIT(addr, cnt) \
    asm volatile("mbarrier.init.shared.b64 [%0], %1;" :: "r"(addr), "r"(cnt) : "memory")

#define MBAR_TX(addr, bytes) \
    asm volatile("mbarrier.arrive.expect_tx.shared.b64 _, [%0], %1;" \
                 :: "r"(addr), "r"(bytes) : "memory")

#define TMA_G2S(dst, src, bytes, mbar) \
    asm volatile("cp.async.bulk.shared::cluster.global.mbarrier::complete_tx::bytes " \
                 "[%0], [%1], %2, [%3];" \
                 :: "r"(dst), "l"(src), "r"(bytes), "r"(mbar) : "memory")

#define MBAR_WAIT(addr, ph) do {                                              \
    asm volatile("{\n\t.reg .pred p;\n\t"                                     \
                 "W_%=:\n\t"                                                  \
                 "mbarrier.try_wait.parity.acquire.cta.shared::cta.b64 p, [%0], %1, 0x989680;\n\t" \
                 "@!p bra W_%=;\n\t}"                                         \
                 :: "r"(addr), "r"(ph) : "memory");                           \
} while (0)

#define FENCE_ASYNC() \
    asm volatile("fence.proxy.async.shared::cta;" ::: "memory")

// ---------------------------------------------------------------------------
// Grid-wide barrier for a fully co-resident persistent grid.
// ---------------------------------------------------------------------------
__device__ __forceinline__ void grid_barrier()
{
    __syncthreads();
    if (threadIdx.x == 0) {
        __threadfence();
        unsigned gen = *(volatile unsigned*)&g_gen;
        if (atomicAdd(&g_count, 1) == NBLK - 1) {
            g_count = 0;
            __threadfence();
            atomicExch(&g_gen, gen + 1);
        } else {
            while (*(volatile unsigned*)&g_gen == gen) { }
            __threadfence();
        }
    }
    __syncthreads();
}

// ---------------------------------------------------------------------------
// Fused persistent kernel: LN/mix -> 4x matvec -> wkv -> Wo matvec.
// 512 blocks x 256 threads, all co-resident (launch_bounds(256,4)).
// ---------------------------------------------------------------------------
__global__ __launch_bounds__(NTHR, 4) void rwkv_fused(
    const float* __restrict__ x,     const float* __restrict__ state1,
    const float* __restrict__ state2,
    const float* __restrict__ tmk,   const float* __restrict__ tmv,
    const float* __restrict__ tmr,   const float* __restrict__ tmg,
    const float* __restrict__ tdec,  const float* __restrict__ tfir,
    const float* __restrict__ Wr,    const float* __restrict__ Wk,
    const float* __restrict__ Wv,    const float* __restrict__ Wg,
    const float* __restrict__ Wo,
    const float* __restrict__ ln1w,  const float* __restrict__ ln1b,
    const float* __restrict__ lnxw,  const float* __restrict__ lnxb,
    float* __restrict__ out, float* __restrict__ state1_out,
    float* __restrict__ state2_out)
{
    __shared__ __align__(128) float wbuf[2][D];          // 2 x 16 KB TMA buffers
    __shared__ __align__(16)  float pw[16][S];           // float4-accessed!
    __shared__ __align__(8) unsigned long long mbar_s[2];
    __shared__ float part[2][8];
    __shared__ float ra[8], rb[8];
    __shared__ float s_mean, s_rstd;
    __shared__ float sk[S], sr[S], stf[S], sdec[S], sw[S];

    const int tid = threadIdx.x, bid = blockIdx.x;
    const int warp = tid >> 5, lane = tid & 31;
    const unsigned mb0 = smem_u32(&mbar_s[0]);
    const unsigned mb1 = smem_u32(&mbar_s[1]);
    unsigned pb0 = 0, pb1 = 0;

    if (tid == 0) {
        MBAR_INIT(mb0, 1);
        MBAR_INIT(mb1, 1);
        FENCE_ASYNC();
        // Pre-issue phase-2 task 0 (Wr row bid) — weights don't depend on LN.
        MBAR_TX(mb0, (unsigned)(D * 4));
        TMA_G2S(smem_u32(wbuf[0]), Wr + (size_t)bid * D, (unsigned)(D * 4), mb0);
    }
    __syncthreads();

    // ---------------- Phase 1: LN + 4 token-mixes (blocks 0..63) ------------
    if (bid < 64) {
        float s = 0.f, sq = 0.f;
#pragma unroll
        for (int k = 0; k < 4; k++) {
            float4 v = ((const float4*)x)[tid + k * 256];
            s  += v.x + v.y + v.z + v.w;
            sq += v.x * v.x + v.y * v.y + v.z * v.z + v.w * v.w;
        }
#pragma unroll
        for (int o = 16; o; o >>= 1) {
            s  += __shfl_xor_sync(0xffffffffu, s, o);
            sq += __shfl_xor_sync(0xffffffffu, sq, o);
        }
        if (lane == 0) { ra[warp] = s; rb[warp] = sq; }
        __syncthreads();
        if (tid == 0) {
            float ts = 0.f, tq = 0.f;
#pragma unroll
            for (int i = 0; i < 8; i++) { ts += ra[i]; tq += rb[i]; }
            float m   = ts * (1.0f / D);
            float var = tq * (1.0f / D) - m * m;
            s_mean = m;
            s_rstd = rsqrtf(var + EPSF);
        }
        __syncthreads();
        if (tid < 64) {
            int idx = bid * 64 + tid;
            float m = s_mean, rstd = s_rstd;
            float xi = x[idx];
            float xx = (xi - m) * rstd * ln1w[idx] + ln1b[idx];
            state1_out[idx] = xx;
            float st = state1[idx];
            float tr = tmr[idx], tk = tmk[idx], tv = tmv[idx], tg = tmg[idx];
            g_mix[0 * D + idx] = st * (1.f - tr) + xx * tr;
            g_mix[1 * D + idx] = st * (1.f - tk) + xx * tk;
            g_mix[2 * D + idx] = st * (1.f - tv) + xx * tv;
            g_mix[3 * D + idx] = st * (1.f - tg) + xx * tg;
        }
    }
    grid_barrier();

    // ---------------- Phase 2: 16384-row matvec (Wr,Wk,Wv,Wg) --------------
    // Task t = bid + 512*i: m = i>>3, row = bid + 512*(i&7). 32 rows/block.
#pragma unroll 1
    for (int i = 0; i < 32; i++) {
        int cb = i & 1;
        if (i + 1 < 32 && tid == 0) {
            int i2 = i + 1;
            int m2 = i2 >> 3, row2 = bid + ((i2 & 7) << 9);
            const float* W2 = (m2 == 0) ? Wr : (m2 == 1) ? Wk
                            : (m2 == 2) ? Wv : Wg;
            unsigned mbn = (i2 & 1) ? mb1 : mb0;
            FENCE_ASYNC();
            MBAR_TX(mbn, (unsigned)(D * 4));
            TMA_G2S(smem_u32(wbuf[i2 & 1]), W2 + (size_t)row2 * D,
                    (unsigned)(D * 4), mbn);
        }
        int m = i >> 3, row = bid + ((i & 7) << 9);
        const float* xp = g_mix + (m << 12) + warp * 512 + lane * 4;
        float4 x0 = *(const float4*)(xp + 0 * 128);
        float4 x1 = *(const float4*)(xp + 1 * 128);
        float4 x2 = *(const float4*)(xp + 2 * 128);
        float4 x3 = *(const float4*)(xp + 3 * 128);

        if (cb) { MBAR_WAIT(mb1, pb1); pb1 ^= 1; }
        else    { MBAR_WAIT(mb0, pb0); pb0 ^= 1; }

        const float* wp = wbuf[cb] + warp * 512 + lane * 4;
        float4 w0 = *(const float4*)(wp + 0 * 128);
        float4 w1 = *(const float4*)(wp + 1 * 128);
        float4 w2 = *(const float4*)(wp + 2 * 128);
        float4 w3 = *(const float4*)(wp + 3 * 128);

        float a0 = w0.x * x0.x + w0.y * x0.y + w0.z * x0.z + w0.w * x0.w;
        float a1 = w1.x * x1.x + w1.y * x1.y + w1.z * x1.z + w1.w * x1.w;
        float a2 = w2.x * x2.x + w2.y * x2.y + w2.z * x2.z + w2.w * x2.w;
        float a3 = w3.x * x3.x + w3.y * x3.y + w3.z * x3.z + w3.w * x3.w;
        float acc = (a0 + a1) + (a2 + a3);
#pragma unroll
        for (int o = 16; o; o >>= 1) acc += __shfl_xor_sync(0xffffffffu, acc, o);

        if (lane == 0) part[cb][warp] = acc;
        __syncthreads();
        if (tid == 0) {
            float r = ((part[cb][0] + part[cb][1]) + (part[cb][2] + part[cb][3]))
                    + ((part[cb][4] + part[cb][5]) + (part[cb][6] + part[cb][7]));
            g_rkvg[(m << 12) + row] = r;
        }
    }

    // Pre-issue phase-4 task 0 (Wo row bid) — overlaps wkv + barriers.
    if (tid == 0) {
        FENCE_ASYNC();
        MBAR_TX(mb0, (unsigned)(D * 4));
        TMA_G2S(smem_u32(wbuf[0]), Wo + (size_t)bid * D, (unsigned)(D * 4), mb0);
    }

    // wkv inputs: prefetch this block's state2 tile while others finish.
    const int jg = tid & 15, ig = tid >> 4;
    float4 s2v[4];
    if (bid < 64) {
        const float4* S2 = (const float4*)(state2 + (size_t)bid * S * S);
#pragma unroll
        for (int di = 0; di < 4; di++)
            s2v[di] = S2[(ig * 4 + di) * 16 + jg];
    }
    grid_barrier();

    // ---------------- Phase 3: wkv + InstanceNorm + SiLU (blocks 0..63) ----
    if (bid < 64) {
        int h = bid;
        float4* S2o = (float4*)(state2_out + (size_t)h * S * S);
        if (tid < S) {
            sr[tid]   = g_rkvg[0 * D + h * S + tid];
            sk[tid]   = g_rkvg[1 * D + h * S + tid];
            stf[tid]  = tfir[h * S + tid];
            sdec[tid] = tdec[h * S + tid];
        }
        float4 vj = ((const float4*)(g_rkvg + 2 * D + h * S))[jg];
        __syncthreads();

        float4 acc = make_float4(0.f, 0.f, 0.f, 0.f);
#pragma unroll
        for (int di = 0; di < 4; di++) {
            int i = ig * 4 + di;
            float ki = sk[i], ri = sr[i], tfi = stf[i], dci = sdec[i];
            float4 s2 = s2v[di];
            float4 kv = make_float4(ki * vj.x, ki * vj.y, ki * vj.z, ki * vj.w);
            float4 so;
            so.x = kv.x + s2.x * dci; so.y = kv.y + s2.y * dci;
            so.z = kv.z + s2.z * dci; so.w = kv.w + s2.w * dci;
            S2o[i * 16 + jg] = so;
            acc.x += ri * (kv.x * tfi + s2.x);
            acc.y += ri * (kv.y * tfi + s2.y);
            acc.z += ri * (kv.z * tfi + s2.z);
            acc.w += ri * (kv.w * tfi + s2.w);
        }
        ((float4*)&pw[ig][0])[jg] = acc;
        __syncthreads();

        if (tid < S) {
            float wsum = 0.f;
#pragma unroll
            for (int g2 = 0; g2 < 16; g2++) wsum += pw[g2][tid];
            sw[tid] = wsum;
        }
        __syncthreads();
        if (tid < S) {
            float s = 0.f, sq = 0.f;
#pragma unroll
            for (int i = 0; i < S; i++) { float u = sw[i]; s += u; sq += u * u; }
            float mu  = s * (1.0f / S);
            float var = sq * (1.0f / S) - mu * mu;
            float xn  = (sw[tid] - mu) * rsqrtf(var + EPSF);
            float g    = g_rkvg[3 * D + h * S + tid];
            float gate = g / (1.f + expf(-g));   // SiLU
            g_y[h * S + tid] = (xn * lnxw[h * S + tid] + lnxb[h * S + tid]) * gate;
        }
    }
    grid_barrier();

    // ---------------- Phase 4: out = x + Wo @ y (8 rows/block) -------------
    const float* yp = g_y + warp * 512 + lane * 4;
    float4 y0 = *(const float4*)(yp + 0 * 128);
    float4 y1 = *(const float4*)(yp + 1 * 128);
    float4 y2 = *(const float4*)(yp + 2 * 128);
    float4 y3 = *(const float4*)(yp + 3 * 128);

#pragma unroll 1
    for (int i = 0; i < 8; i++) {
        int cb = i & 1;
        if (i + 1 < 8 && tid == 0) {
            int row2 = bid + ((i + 1) << 9);
            unsigned mbn = ((i + 1) & 1) ? mb1 : mb0;
            FENCE_ASYNC();
            MBAR_TX(mbn, (unsigned)(D * 4));
            TMA_G2S(smem_u32(wbuf[(i + 1) & 1]), Wo + (size_t)row2 * D,
                    (unsigned)(D * 4), mbn);
        }
        int row = bid + (i << 9);

        if (cb) { MBAR_WAIT(mb1, pb1); pb1 ^= 1; }
        else    { MBAR_WAIT(mb0, pb0); pb0 ^= 1; }

        const float* wp = wbuf[cb] + warp * 512 + lane * 4;
        float4 w0 = *(const float4*)(wp + 0 * 128);
        float4 w1 = *(const float4*)(wp + 1 * 128);
        float4 w2 = *(const float4*)(wp + 2 * 128);
        float4 w3 = *(const float4*)(wp + 3 * 128);

        float a0 = w0.x * y0.x + w0.y * y0.y + w0.z * y0.z + w0.w * y0.w;
        float a1 = w1.x * y1.x + w1.y * y1.y + w1.z * y1.z + w1.w * y1.w;
        float a2 = w2.x * y2.x + w2.y * y2.y + w2.z * y2.z + w2.w * y2.w;
        float a3 = w3.x * y3.x + w3.y * y3.y + w3.z * y3.z + w3.w * y3.w;
        float acc = (a0 + a1) + (a2 + a3);
#pragma unroll
        for (int o = 16; o; o >>= 1) acc += __shfl_xor_sync(0xffffffffu, acc, o);

        if (lane == 0) part[cb][warp] = acc;
        __syncthreads();
        if (tid == 0) {
            float r = ((part[cb][0] + part[cb][1]) + (part[cb][2] + part[cb][3]))
                    + ((part[cb][4] + part[cb][5]) + (part[cb][6] + part[cb][7]));
            out[row] = x[row] + r;
        }
    }
}

// ---------------------------------------------------------------------------
extern "C" void kernel_launch(void* const* d_in, const int* in_sizes, int n_in,
                              void* d_out, int out_size)
{
    const float* x      = (const float*)d_in[0];
    const float* state1 = (const float*)d_in[1];
    const float* state2 = (const float*)d_in[2];
    const float* tmk    = (const float*)d_in[3];
    const float* tmv    = (const float*)d_in[4];
    const float* tmr    = (const float*)d_in[5];
    const float* tmg    = (const float*)d_in[6];
    const float* tdec   = (const float*)d_in[7];
    const float* tfir   = (const float*)d_in[8];
    const float* Wr     = (const float*)d_in[9];
    const float* Wk     = (const float*)d_in[10];
    const float* Wv     = (const float*)d_in[11];
    const float* Wg     = (const float*)d_in[12];
    const float* Wo     = (const float*)d_in[13];
    const float* ln1w   = (const float*)d_in[14];
    const float* ln1b   = (const float*)d_in[15];
    const float* lnxw   = (const float*)d_in[16];
    const float* lnxb   = (const float*)d_in[17];

    float* out        = (float*)d_out;         // [0, D)
    float* state1_out = out + D;               // [D, 2D)
    float* state2_out = out + 2 * D;           // [2D, 2D + H*S*S)

    rwkv_fused<<<NBLK, NTHR>>>(x, state1, state2, tmk, tmv, tmr, tmg,
                               tdec, tfir, Wr, Wk, Wv, Wg, Wo,
                               ln1w, ln1b, lnxw, lnxb,
                               out, state1_out, state2_out);
}